// round 3
// baseline (speedup 1.0000x reference)
#include <cuda_runtime.h>

// Problem constants
#define SEQ    4096
#define DM     1024
#define NH     16
#define DHD    64
#define D3     3072   // 3 * DM

// Scratch for kqv = x @ w_kqv   (chunk order: K | Q | V)
__device__ float g_kqv[SEQ * D3];

// ---------------------------------------------------------------------------
// Kernel 1: fp32 GEMM  g_kqv[4096,3072] = x[4096,1024] @ w[1024,3072]
// 128x128 block tile, BK=16, 256 threads, 8x8 per thread (split fragments)
// ---------------------------------------------------------------------------
__global__ __launch_bounds__(256) void gemm_kqv_kernel(const float* __restrict__ A,
                                                       const float* __restrict__ B) {
    __shared__ float As[16][132];   // A transposed: As[k][m]
    __shared__ float Bs[16][132];   // Bs[k][n]

    const int tid = threadIdx.x;
    const int tx = tid & 15, ty = tid >> 4;
    const int bm = blockIdx.y * 128, bn = blockIdx.x * 128;

    const int arow = tid >> 2;          // 0..63
    const int acol = (tid & 3) << 2;    // 0,4,8,12
    const int brow = tid >> 5;          // 0..7
    const int bcol = (tid & 31) << 2;   // 0..124

    float acc[8][8];
#pragma unroll
    for (int i = 0; i < 8; i++)
#pragma unroll
        for (int j = 0; j < 8; j++) acc[i][j] = 0.f;

    for (int k0 = 0; k0 < DM; k0 += 16) {
#pragma unroll
        for (int p = 0; p < 2; p++) {
            int r = arow + p * 64;
            float4 a4 = *(const float4*)(A + (size_t)(bm + r) * DM + k0 + acol);
            As[acol + 0][r] = a4.x;
            As[acol + 1][r] = a4.y;
            As[acol + 2][r] = a4.z;
            As[acol + 3][r] = a4.w;
        }
#pragma unroll
        for (int p = 0; p < 2; p++) {
            int r = brow + p * 8;
            *(float4*)(&Bs[r][bcol]) = *(const float4*)(B + (size_t)(k0 + r) * D3 + bn + bcol);
        }
        __syncthreads();

#pragma unroll
        for (int kk = 0; kk < 16; kk++) {
            float4 a0 = *(const float4*)(&As[kk][ty * 4]);
            float4 a1 = *(const float4*)(&As[kk][64 + ty * 4]);
            float4 b0 = *(const float4*)(&Bs[kk][tx * 4]);
            float4 b1 = *(const float4*)(&Bs[kk][64 + tx * 4]);
            float av[8] = {a0.x, a0.y, a0.z, a0.w, a1.x, a1.y, a1.z, a1.w};
            float bv[8] = {b0.x, b0.y, b0.z, b0.w, b1.x, b1.y, b1.z, b1.w};
#pragma unroll
            for (int i = 0; i < 8; i++)
#pragma unroll
                for (int j = 0; j < 8; j++) acc[i][j] = fmaf(av[i], bv[j], acc[i][j]);
        }
        __syncthreads();
    }

#pragma unroll
    for (int i = 0; i < 8; i++) {
        int r = bm + ((i < 4) ? (ty * 4 + i) : (64 + ty * 4 + (i - 4)));
        float* crow = g_kqv + (size_t)r * D3 + bn;
        *(float4*)(crow + tx * 4)      = make_float4(acc[i][0], acc[i][1], acc[i][2], acc[i][3]);
        *(float4*)(crow + 64 + tx * 4) = make_float4(acc[i][4], acc[i][5], acc[i][6], acc[i][7]);
    }
}

// ---------------------------------------------------------------------------
// Kernel 2: flash attention with ALiBi + causal mask, fp32
// grid = (64 q-tiles, 16 heads), 256 threads (16x16), BM=BKV=64, dh=64
// smem: Qs[64][68] | KPs[64][68] (K tile, reused as P tile) | Vs[64][68]
// ---------------------------------------------------------------------------
#define LDP 68

__global__ __launch_bounds__(256) void attn_kernel(float* __restrict__ out) {
    extern __shared__ float sm[];
    float* Qs  = sm;                // [64][LDP], pre-scaled by 1/32
    float* KPs = sm + 64 * LDP;     // K tile, then reused as P tile
    float* Vs  = sm + 2 * 64 * LDP;

    const int tid = threadIdx.x;
    const int tx = tid & 15, ty = tid >> 4;
    const int h = blockIdx.y;
    // reversed so heaviest (largest q0) tiles launch first
    const int qt = (int)gridDim.x - 1 - (int)blockIdx.x;
    const int q0 = qt * 64;
    const float slope = exp2f(-0.5f * (float)(h + 1));   // 2^(-(h+1)/2)

    const int lr = tid >> 4;          // load row-within-pass 0..15
    const int lc = (tid & 15) << 2;   // load float4 column 0..60

    // Load Q tile (offset DM in kqv: chunk order K|Q|V), pre-scaled by 1/sqrt(D)=1/32
#pragma unroll
    for (int p = 0; p < 4; p++) {
        int r = p * 16 + lr;
        float4 q4 = *(const float4*)(g_kqv + (size_t)(q0 + r) * D3 + DM + h * DHD + lc);
        q4.x *= 0.03125f; q4.y *= 0.03125f; q4.z *= 0.03125f; q4.w *= 0.03125f;
        *(float4*)(&Qs[r * LDP + lc]) = q4;
    }

    float o[4][4];
    float m[4], l[4];
#pragma unroll
    for (int i = 0; i < 4; i++) {
        m[i] = -3.0e38f;
        l[i] = 0.f;
#pragma unroll
        for (int j = 0; j < 4; j++) o[i][j] = 0.f;
    }

    const int ntiles = qt + 1;   // causal: only kv tiles with kv0 <= q0
    for (int t = 0; t < ntiles; t++) {
        const int kv0 = t * 64;
        // Load K (offset 0) and V (offset 2*DM) tiles, coalesced float4
#pragma unroll
        for (int p = 0; p < 4; p++) {
            int r = p * 16 + lr;
            const float* base = g_kqv + (size_t)(kv0 + r) * D3 + h * DHD + lc;
            *(float4*)(&KPs[r * LDP + lc]) = *(const float4*)(base);
            *(float4*)(&Vs[r * LDP + lc])  = *(const float4*)(base + 2 * DM);
        }
        __syncthreads();

        // S = Q K^T  (rows: ty*4+i, cols: tx+16*j for conflict-free smem reads)
        float s[4][4];
#pragma unroll
        for (int i = 0; i < 4; i++)
#pragma unroll
            for (int j = 0; j < 4; j++) s[i][j] = 0.f;

#pragma unroll
        for (int d4 = 0; d4 < 16; d4++) {
            float4 qv[4], kv[4];
#pragma unroll
            for (int i = 0; i < 4; i++)
                qv[i] = *(const float4*)(&Qs[(ty * 4 + i) * LDP + d4 * 4]);
#pragma unroll
            for (int j = 0; j < 4; j++)
                kv[j] = *(const float4*)(&KPs[(tx + 16 * j) * LDP + d4 * 4]);
#pragma unroll
            for (int i = 0; i < 4; i++)
#pragma unroll
                for (int j = 0; j < 4; j++) {
                    s[i][j] = fmaf(qv[i].x, kv[j].x, s[i][j]);
                    s[i][j] = fmaf(qv[i].y, kv[j].y, s[i][j]);
                    s[i][j] = fmaf(qv[i].z, kv[j].z, s[i][j]);
                    s[i][j] = fmaf(qv[i].w, kv[j].w, s[i][j]);
                }
        }
        __syncthreads();   // everyone done reading K before it becomes P

        const bool diag = (t == ntiles - 1);   // only tile where j > i possible
#pragma unroll
        for (int i = 0; i < 4; i++) {
            const int gi = q0 + ty * 4 + i;
            float mx = -3.0e38f;
#pragma unroll
            for (int j = 0; j < 4; j++) {
                const int gj = kv0 + tx + 16 * j;
                float sc = s[i][j] + slope * (float)(gj - gi);   // ALiBi bias
                if (diag && gj > gi) sc = -3.0e38f;              // causal mask
                s[i][j] = sc;
                mx = fmaxf(mx, sc);
            }
            // reduce over the 16 lanes sharing this row (aligned 16-lane group)
#pragma unroll
            for (int off = 8; off >= 1; off >>= 1)
                mx = fmaxf(mx, __shfl_xor_sync(0xffffffffu, mx, off));

            const float m_new = fmaxf(m[i], mx);
            const float alpha = __expf(m[i] - m_new);
            m[i] = m_new;

            float rs = 0.f;
#pragma unroll
            for (int j = 0; j < 4; j++) {
                float pj = __expf(s[i][j] - m_new);
                s[i][j] = pj;
                rs += pj;
            }
#pragma unroll
            for (int off = 8; off >= 1; off >>= 1)
                rs += __shfl_xor_sync(0xffffffffu, rs, off);

            l[i] = l[i] * alpha + rs;
#pragma unroll
            for (int j = 0; j < 4; j++) o[i][j] *= alpha;
            // stage P into smem (conflict-free: consecutive tx -> consecutive banks)
#pragma unroll
            for (int j = 0; j < 4; j++)
                KPs[(ty * 4 + i) * LDP + tx + 16 * j] = s[i][j];
        }
        __syncthreads();

        // O += P @ V   (O cols: tx*4+j contiguous)
#pragma unroll
        for (int c = 0; c < 64; c += 4) {
            float4 pv[4], vv[4];
#pragma unroll
            for (int i = 0; i < 4; i++)
                pv[i] = *(const float4*)(&KPs[(ty * 4 + i) * LDP + c]);
#pragma unroll
            for (int cc = 0; cc < 4; cc++)
                vv[cc] = *(const float4*)(&Vs[(c + cc) * LDP + tx * 4]);
#pragma unroll
            for (int i = 0; i < 4; i++) {
                float pe[4] = {pv[i].x, pv[i].y, pv[i].z, pv[i].w};
#pragma unroll
                for (int cc = 0; cc < 4; cc++) {
                    o[i][0] = fmaf(pe[cc], vv[cc].x, o[i][0]);
                    o[i][1] = fmaf(pe[cc], vv[cc].y, o[i][1]);
                    o[i][2] = fmaf(pe[cc], vv[cc].z, o[i][2]);
                    o[i][3] = fmaf(pe[cc], vv[cc].w, o[i][3]);
                }
            }
        }
        __syncthreads();   // done reading P/V before next tile overwrites
    }

    // Epilogue: normalize and write out[s, h*64 + d]
#pragma unroll
    for (int i = 0; i < 4; i++) {
        const float rl = 1.f / l[i];
        *(float4*)(out + (size_t)(q0 + ty * 4 + i) * DM + h * DHD + tx * 4) =
            make_float4(o[i][0] * rl, o[i][1] * rl, o[i][2] * rl, o[i][3] * rl);
    }
}

// ---------------------------------------------------------------------------
// Launch
// ---------------------------------------------------------------------------
extern "C" void kernel_launch(void* const* d_in, const int* in_sizes, int n_in,
                              void* d_out, int out_size) {
    const float* x = (const float*)d_in[0];   // [1, 4096, 1024]
    const float* w = (const float*)d_in[1];   // [1024, 3072]
    float* out = (float*)d_out;               // [1, 4096, 1024]

    const int attn_smem = 3 * 64 * LDP * (int)sizeof(float);   // 52224 B
    cudaFuncSetAttribute(attn_kernel, cudaFuncAttributeMaxDynamicSharedMemorySize, attn_smem);

    gemm_kqv_kernel<<<dim3(D3 / 128, SEQ / 128), 256>>>(x, w);
    attn_kernel<<<dim3(SEQ / 64, NH), 256, attn_smem>>>(out);
}

// round 4
// speedup vs baseline: 3.9816x; 3.9816x over previous
#include <cuda_runtime.h>
#include <cuda_bf16.h>

#define SEQ 4096
#define DM  1024
#define NH  16
#define DHD 64
#define D3  3072

// bf16 hi/lo split scratch
__device__ __nv_bfloat16 g_xh[SEQ * DM];
__device__ __nv_bfloat16 g_xl[SEQ * DM];
__device__ __nv_bfloat16 g_wh[DM * D3];
__device__ __nv_bfloat16 g_wl[DM * D3];
__device__ __nv_bfloat16 g_kh[SEQ * D3];   // kqv hi  (chunk order K|Q|V)
__device__ __nv_bfloat16 g_kl[SEQ * D3];   // kqv lo

// ---------------------------------------------------------------------------
// helpers
// ---------------------------------------------------------------------------
static __device__ __forceinline__ unsigned s2u(const void* p) {
    return (unsigned)__cvta_generic_to_shared(p);
}
static __device__ __forceinline__ void ldsm4(unsigned* r, unsigned a) {
    asm volatile("ldmatrix.sync.aligned.m8n8.x4.shared.b16 {%0,%1,%2,%3}, [%4];"
                 : "=r"(r[0]), "=r"(r[1]), "=r"(r[2]), "=r"(r[3]) : "r"(a));
}
static __device__ __forceinline__ void ldsm4t(unsigned* r, unsigned a) {
    asm volatile("ldmatrix.sync.aligned.m8n8.x4.trans.shared.b16 {%0,%1,%2,%3}, [%4];"
                 : "=r"(r[0]), "=r"(r[1]), "=r"(r[2]), "=r"(r[3]) : "r"(a));
}
static __device__ __forceinline__ void mma16816(float* c, const unsigned* a, const unsigned* b) {
    asm volatile("mma.sync.aligned.m16n8k16.row.col.f32.bf16.bf16.f32 "
                 "{%0,%1,%2,%3}, {%4,%5,%6,%7}, {%8,%9}, {%0,%1,%2,%3};"
                 : "+f"(c[0]), "+f"(c[1]), "+f"(c[2]), "+f"(c[3])
                 : "r"(a[0]), "r"(a[1]), "r"(a[2]), "r"(a[3]), "r"(b[0]), "r"(b[1]));
}
// split two fp32 into packed bf16 hi-pair and lo-pair (elem0 in low half)
static __device__ __forceinline__ void split2(float v0, float v1, unsigned& hi, unsigned& lo) {
    __nv_bfloat16 h0 = __float2bfloat16(v0), h1 = __float2bfloat16(v1);
    __nv_bfloat16 l0 = __float2bfloat16(v0 - __bfloat162float(h0));
    __nv_bfloat16 l1 = __float2bfloat16(v1 - __bfloat162float(h1));
    hi = (unsigned)__bfloat16_as_ushort(h0) | ((unsigned)__bfloat16_as_ushort(h1) << 16);
    lo = (unsigned)__bfloat16_as_ushort(l0) | ((unsigned)__bfloat16_as_ushort(l1) << 16);
}

// ---------------------------------------------------------------------------
// Kernel 0: fp32 -> bf16 hi/lo split
// ---------------------------------------------------------------------------
__global__ void split_kernel(const float* __restrict__ src,
                             __nv_bfloat16* __restrict__ hi,
                             __nv_bfloat16* __restrict__ lo, int n4) {
    int i = blockIdx.x * blockDim.x + threadIdx.x;
    if (i >= n4) return;
    float4 v = ((const float4*)src)[i];
    unsigned h0, l0, h1, l1;
    split2(v.x, v.y, h0, l0);
    split2(v.z, v.w, h1, l1);
    ((uint2*)hi)[i] = make_uint2(h0, h1);
    ((uint2*)lo)[i] = make_uint2(l0, l1);
}

// ---------------------------------------------------------------------------
// Kernel 1: kqv = x @ w  via bf16-split mma (3 MMAs per product)
// CTA 128x128, BK=32, 8 warps (2m x 4n), warp tile 64x32
// ---------------------------------------------------------------------------
__global__ __launch_bounds__(256) void gemm_kqv() {
    __shared__ __align__(16) __nv_bfloat16 Ash[2][128][40];
    __shared__ __align__(16) __nv_bfloat16 Bsh[2][32][136];
    const int tid = threadIdx.x, lane = tid & 31, wid = tid >> 5;
    const int bm = blockIdx.y * 128, bn = blockIdx.x * 128;
    const int wm = (wid >> 2) * 64, wn = (wid & 3) * 32;

    float c[4][4][4];
#pragma unroll
    for (int i = 0; i < 4; i++)
#pragma unroll
        for (int j = 0; j < 4; j++)
#pragma unroll
            for (int e = 0; e < 4; e++) c[i][j][e] = 0.f;

    for (int k0 = 0; k0 < DM; k0 += 32) {
#pragma unroll
        for (int p = 0; p < 2; p++) {
            int idx = tid + p * 256;
            int ar = idx >> 2, ac = (idx & 3) * 8;
            *(uint4*)&Ash[0][ar][ac] = *(const uint4*)&g_xh[(size_t)(bm + ar) * DM + k0 + ac];
            *(uint4*)&Ash[1][ar][ac] = *(const uint4*)&g_xl[(size_t)(bm + ar) * DM + k0 + ac];
            int br = idx >> 4, bc = (idx & 15) * 8;
            *(uint4*)&Bsh[0][br][bc] = *(const uint4*)&g_wh[(size_t)(k0 + br) * D3 + bn + bc];
            *(uint4*)&Bsh[1][br][bc] = *(const uint4*)&g_wl[(size_t)(k0 + br) * D3 + bn + bc];
        }
        __syncthreads();
#pragma unroll
        for (int ks = 0; ks < 2; ks++) {
            const int kk = ks * 16;
            unsigned ah[4][4], al[4][4];
#pragma unroll
            for (int mt = 0; mt < 4; mt++) {
                int r = wm + mt * 16 + (lane & 15), cc = kk + (lane >> 4) * 8;
                ldsm4(ah[mt], s2u(&Ash[0][r][cc]));
                ldsm4(al[mt], s2u(&Ash[1][r][cc]));
            }
#pragma unroll
            for (int np = 0; np < 2; np++) {
                int n0 = wn + np * 16;
                int r = kk + (lane & 15), cc = n0 + (lane >> 4) * 8;
                unsigned th[4], tl[4];
                ldsm4t(th, s2u(&Bsh[0][r][cc]));   // (th0,th1)=ntile n0, (th2,th3)=ntile n0+8
                ldsm4t(tl, s2u(&Bsh[1][r][cc]));
                unsigned bh0[2] = {th[0], th[1]}, bh1[2] = {th[2], th[3]};
                unsigned bl0[2] = {tl[0], tl[1]}, bl1[2] = {tl[2], tl[3]};
#pragma unroll
                for (int mt = 0; mt < 4; mt++) {
                    mma16816(c[mt][np * 2],     ah[mt], bh0);
                    mma16816(c[mt][np * 2],     ah[mt], bl0);
                    mma16816(c[mt][np * 2],     al[mt], bh0);
                    mma16816(c[mt][np * 2 + 1], ah[mt], bh1);
                    mma16816(c[mt][np * 2 + 1], ah[mt], bl1);
                    mma16816(c[mt][np * 2 + 1], al[mt], bh1);
                }
            }
        }
        __syncthreads();
    }
    // epilogue: write kqv as bf16 hi/lo
#pragma unroll
    for (int mt = 0; mt < 4; mt++) {
        int r0 = bm + wm + mt * 16 + (lane >> 2);
#pragma unroll
        for (int nt = 0; nt < 4; nt++) {
            int col = bn + wn + nt * 8 + (lane & 3) * 2;
            unsigned h, l;
            split2(c[mt][nt][0], c[mt][nt][1], h, l);
            *(unsigned*)&g_kh[(size_t)r0 * D3 + col] = h;
            *(unsigned*)&g_kl[(size_t)r0 * D3 + col] = l;
            split2(c[mt][nt][2], c[mt][nt][3], h, l);
            *(unsigned*)&g_kh[(size_t)(r0 + 8) * D3 + col] = h;
            *(unsigned*)&g_kl[(size_t)(r0 + 8) * D3 + col] = l;
        }
    }
}

// ---------------------------------------------------------------------------
// Kernel 2: flash attention, bf16-split mma, ALiBi + causal
// grid (64 qtiles, 16 heads), 128 threads (4 warps), BM=BN=64
// ---------------------------------------------------------------------------
#define LDA 72

__global__ __launch_bounds__(128) void attn_kernel(float* __restrict__ out) {
    extern __shared__ __align__(16) __nv_bfloat16 sm[];
    __nv_bfloat16* KH = sm;
    __nv_bfloat16* KL = sm + 64 * LDA;
    __nv_bfloat16* VH = sm + 2 * 64 * LDA;
    __nv_bfloat16* VL = sm + 3 * 64 * LDA;
    __nv_bfloat16* PH = sm + 4 * 64 * LDA;   // Q staged here first, then P
    __nv_bfloat16* PL = sm + 5 * 64 * LDA;

    const int tid = threadIdx.x, lane = tid & 31, wid = tid >> 5;
    const int h = blockIdx.y;
    const int qt = (int)gridDim.x - 1 - (int)blockIdx.x;   // heavy tiles first
    const int q0 = qt * 64;
    const int wr = wid * 16;
    const float slope = exp2f(-0.5f * (float)(h + 1));

    {   // stage Q tile into P region
        const size_t qoff = (size_t)q0 * D3 + DM + h * DHD;
#pragma unroll
        for (int p = 0; p < 4; p++) {
            int idx = tid + p * 128;
            int r = idx >> 3, cc = (idx & 7) * 8;
            *(uint4*)&PH[r * LDA + cc] = *(const uint4*)&g_kh[qoff + (size_t)r * D3 + cc];
            *(uint4*)&PL[r * LDA + cc] = *(const uint4*)&g_kl[qoff + (size_t)r * D3 + cc];
        }
    }
    __syncthreads();

    unsigned qh[4][4], ql[4][4];   // resident Q fragments
#pragma unroll
    for (int ks = 0; ks < 4; ks++) {
        int r = wr + (lane & 15), cc = ks * 16 + (lane >> 4) * 8;
        ldsm4(qh[ks], s2u(&PH[r * LDA + cc]));
        ldsm4(ql[ks], s2u(&PL[r * LDA + cc]));
    }
    // no CTA barrier needed: each warp later overwrites only its OWN P rows

    float o[8][4];
#pragma unroll
    for (int nt = 0; nt < 8; nt++)
#pragma unroll
        for (int e = 0; e < 4; e++) o[nt][e] = 0.f;
    float mrow0 = -1e30f, mrow1 = -1e30f, lrow0 = 0.f, lrow1 = 0.f;

    for (int t = 0; t <= qt; t++) {
        const int kv0 = t * 64;
        {   // cooperative K/V tile load
            const size_t koff = (size_t)kv0 * D3 + h * DHD;
#pragma unroll
            for (int p = 0; p < 4; p++) {
                int idx = tid + p * 128;
                int r = idx >> 3, cc = (idx & 7) * 8;
                size_t g = koff + (size_t)r * D3 + cc;
                *(uint4*)&KH[r * LDA + cc] = *(const uint4*)&g_kh[g];
                *(uint4*)&KL[r * LDA + cc] = *(const uint4*)&g_kl[g];
                *(uint4*)&VH[r * LDA + cc] = *(const uint4*)&g_kh[g + 2 * DM];
                *(uint4*)&VL[r * LDA + cc] = *(const uint4*)&g_kl[g + 2 * DM];
            }
        }
        __syncthreads();

        // --- S = (Q K^T) with 3-MMA split ---
        float s[8][4];
#pragma unroll
        for (int nt = 0; nt < 8; nt++)
#pragma unroll
            for (int e = 0; e < 4; e++) s[nt][e] = 0.f;
#pragma unroll
        for (int ks = 0; ks < 4; ks++) {
#pragma unroll
            for (int np = 0; np < 4; np++) {
                int r = np * 16 + (lane & 15), cc = ks * 16 + (lane >> 4) * 8;
                unsigned th[4], tl[4];
                ldsm4(th, s2u(&KH[r * LDA + cc]));   // (th0,th2)=ntile 2np, (th1,th3)=2np+1
                ldsm4(tl, s2u(&KL[r * LDA + cc]));
                unsigned f0h[2] = {th[0], th[2]}, f1h[2] = {th[1], th[3]};
                unsigned f0l[2] = {tl[0], tl[2]}, f1l[2] = {tl[1], tl[3]};
                mma16816(s[np * 2],     qh[ks], f0h);
                mma16816(s[np * 2],     qh[ks], f0l);
                mma16816(s[np * 2],     ql[ks], f0h);
                mma16816(s[np * 2 + 1], qh[ks], f1h);
                mma16816(s[np * 2 + 1], qh[ks], f1l);
                mma16816(s[np * 2 + 1], ql[ks], f1h);
            }
        }

        // --- online softmax (fp32) ---
        const bool diag = (t == qt);
        const int gi0 = q0 + wr + (lane >> 2);
        float ml0 = -1e30f, ml1 = -1e30f;
#pragma unroll
        for (int nt = 0; nt < 8; nt++) {
#pragma unroll
            for (int e = 0; e < 2; e++) {
                int gj = kv0 + nt * 8 + (lane & 3) * 2 + e;
                float v0 = fmaf(slope, (float)(gj - gi0), s[nt][e] * 0.03125f);
                if (diag && gj > gi0) v0 = -1e30f;
                s[nt][e] = v0; ml0 = fmaxf(ml0, v0);
                float v1 = fmaf(slope, (float)(gj - (gi0 + 8)), s[nt][2 + e] * 0.03125f);
                if (diag && gj > gi0 + 8) v1 = -1e30f;
                s[nt][2 + e] = v1; ml1 = fmaxf(ml1, v1);
            }
        }
        ml0 = fmaxf(ml0, __shfl_xor_sync(0xffffffffu, ml0, 1));
        ml0 = fmaxf(ml0, __shfl_xor_sync(0xffffffffu, ml0, 2));
        ml1 = fmaxf(ml1, __shfl_xor_sync(0xffffffffu, ml1, 1));
        ml1 = fmaxf(ml1, __shfl_xor_sync(0xffffffffu, ml1, 2));
        float mn0 = fmaxf(mrow0, ml0), mn1 = fmaxf(mrow1, ml1);
        float a0 = __expf(mrow0 - mn0), a1 = __expf(mrow1 - mn1);
        mrow0 = mn0; mrow1 = mn1;
        float rs0 = 0.f, rs1 = 0.f;
#pragma unroll
        for (int nt = 0; nt < 8; nt++) {
#pragma unroll
            for (int e = 0; e < 2; e++) {
                float p0 = __expf(s[nt][e] - mn0);     s[nt][e] = p0;     rs0 += p0;
                float p1 = __expf(s[nt][2 + e] - mn1); s[nt][2 + e] = p1; rs1 += p1;
            }
        }
        rs0 += __shfl_xor_sync(0xffffffffu, rs0, 1);
        rs0 += __shfl_xor_sync(0xffffffffu, rs0, 2);
        rs1 += __shfl_xor_sync(0xffffffffu, rs1, 1);
        rs1 += __shfl_xor_sync(0xffffffffu, rs1, 2);
        lrow0 = lrow0 * a0 + rs0;
        lrow1 = lrow1 * a1 + rs1;
#pragma unroll
        for (int nt = 0; nt < 8; nt++) { o[nt][0] *= a0; o[nt][1] *= a0; o[nt][2] *= a1; o[nt][3] *= a1; }

        // --- store P (own warp rows only) as bf16 hi/lo ---
        {
            int r0 = wr + (lane >> 2), col0 = (lane & 3) * 2;
#pragma unroll
            for (int nt = 0; nt < 8; nt++) {
                unsigned hp, lp;
                split2(s[nt][0], s[nt][1], hp, lp);
                *(unsigned*)&PH[r0 * LDA + nt * 8 + col0] = hp;
                *(unsigned*)&PL[r0 * LDA + nt * 8 + col0] = lp;
                split2(s[nt][2], s[nt][3], hp, lp);
                *(unsigned*)&PH[(r0 + 8) * LDA + nt * 8 + col0] = hp;
                *(unsigned*)&PL[(r0 + 8) * LDA + nt * 8 + col0] = lp;
            }
        }
        __syncwarp();

        // --- O += P @ V with 3-MMA split (V via ldmatrix.trans) ---
#pragma unroll
        for (int jk = 0; jk < 4; jk++) {
            unsigned pah[4], pal[4];
            int r = wr + (lane & 15), cc = jk * 16 + (lane >> 4) * 8;
            ldsm4(pah, s2u(&PH[r * LDA + cc]));
            ldsm4(pal, s2u(&PL[r * LDA + cc]));
#pragma unroll
            for (int np = 0; np < 4; np++) {
                int vr = jk * 16 + (lane & 15), vc = np * 16 + (lane >> 4) * 8;
                unsigned th[4], tl[4];
                ldsm4t(th, s2u(&VH[vr * LDA + vc]));   // (th0,th1)=ntile 2np, (th2,th3)=2np+1
                ldsm4t(tl, s2u(&VL[vr * LDA + vc]));
                unsigned f0h[2] = {th[0], th[1]}, f1h[2] = {th[2], th[3]};
                unsigned f0l[2] = {tl[0], tl[1]}, f1l[2] = {tl[2], tl[3]};
                mma16816(o[np * 2],     pah, f0h);
                mma16816(o[np * 2],     pah, f0l);
                mma16816(o[np * 2],     pal, f0h);
                mma16816(o[np * 2 + 1], pah, f1h);
                mma16816(o[np * 2 + 1], pah, f1l);
                mma16816(o[np * 2 + 1], pal, f1h);
            }
        }
        __syncthreads();   // done with K/V before next tile overwrites
    }

    // epilogue
    float rl0 = 1.f / lrow0, rl1 = 1.f / lrow1;
    const int r0 = q0 + wr + (lane >> 2);
#pragma unroll
    for (int nt = 0; nt < 8; nt++) {
        int col = h * DHD + nt * 8 + (lane & 3) * 2;
        *(float2*)&out[(size_t)r0 * DM + col]       = make_float2(o[nt][0] * rl0, o[nt][1] * rl0);
        *(float2*)&out[(size_t)(r0 + 8) * DM + col] = make_float2(o[nt][2] * rl1, o[nt][3] * rl1);
    }
}

// ---------------------------------------------------------------------------
// Launch
// ---------------------------------------------------------------------------
extern "C" void kernel_launch(void* const* d_in, const int* in_sizes, int n_in,
                              void* d_out, int out_size) {
    const float* x = (const float*)d_in[0];   // [1, 4096, 1024]
    const float* w = (const float*)d_in[1];   // [1024, 3072]
    float* out = (float*)d_out;

    __nv_bfloat16 *xh, *xl, *wh, *wl;
    cudaGetSymbolAddress((void**)&xh, g_xh);
    cudaGetSymbolAddress((void**)&xl, g_xl);
    cudaGetSymbolAddress((void**)&wh, g_wh);
    cudaGetSymbolAddress((void**)&wl, g_wl);

    const int attn_smem = 6 * 64 * LDA * (int)sizeof(__nv_bfloat16);   // 55296 B
    cudaFuncSetAttribute(attn_kernel, cudaFuncAttributeMaxDynamicSharedMemorySize, attn_smem);

    const int nx4 = SEQ * DM / 4, nw4 = DM * D3 / 4;
    split_kernel<<<(nx4 + 255) / 256, 256>>>(x, xh, xl, nx4);
    split_kernel<<<(nw4 + 255) / 256, 256>>>(w, wh, wl, nw4);
    gemm_kqv<<<dim3(D3 / 128, SEQ / 128), 256>>>();
    attn_kernel<<<dim3(SEQ / 64, NH), 128, attn_smem>>>(out);
}

// round 5
// speedup vs baseline: 4.8502x; 1.2182x over previous
#include <cuda_runtime.h>

#define SEQ 4096
#define DM  1024
#define NH  16
#define D3  3072
#define LA  68     // attn smem row stride (floats)
#define LG  36     // gemm smem row stride (floats)

// fp32 scratch: kqv = x @ w_kqv, chunk order K | Q | V
__device__ float g_kqv[SEQ * D3];

// ---------------------------------------------------------------------------
// helpers
// ---------------------------------------------------------------------------
static __device__ __forceinline__ unsigned s2u(const void* p) {
    return (unsigned)__cvta_generic_to_shared(p);
}
static __device__ __forceinline__ void ldsm4(unsigned* r, unsigned a) {
    asm volatile("ldmatrix.sync.aligned.m8n8.x4.shared.b16 {%0,%1,%2,%3}, [%4];"
                 : "=r"(r[0]), "=r"(r[1]), "=r"(r[2]), "=r"(r[3]) : "r"(a));
}
static __device__ __forceinline__ float tf32r(float x) {
    unsigned u; asm("cvt.rna.tf32.f32 %0, %1;" : "=r"(u) : "f"(x));
    return __uint_as_float(u);
}
static __device__ __forceinline__ void mma_tf32(float* c, const unsigned* a, const unsigned* b) {
    asm volatile("mma.sync.aligned.m16n8k8.row.col.f32.tf32.tf32.f32 "
                 "{%0,%1,%2,%3}, {%4,%5,%6,%7}, {%8,%9}, {%0,%1,%2,%3};"
                 : "+f"(c[0]), "+f"(c[1]), "+f"(c[2]), "+f"(c[3])
                 : "r"(a[0]), "r"(a[1]), "r"(a[2]), "r"(a[3]), "r"(b[0]), "r"(b[1]));
}
// tf32 A-fragment (16 rows x k8) via b16 ldmatrix trick:
// matrices = (r0,c0),(r0+8,c0),(r0,c0+4),(r0+8,c0+4)  -> regs a0..a3
static __device__ __forceinline__ void ldA(unsigned* a, const float* base, int r0, int c0, int ld) {
    const int lane = threadIdx.x & 31;
    int row = r0 + (lane & 7) + ((lane >> 3) & 1) * 8;
    int col = c0 + (lane >> 4) * 4;
    ldsm4(a, s2u(base + row * ld + col));
}
// tf32 B-fragments for TWO n-tiles (n0, n0+8), one k8 step, from n-major data:
// matrices = (n0,c0),(n0,c0+4),(n0+8,c0),(n0+8,c0+4) -> b[0..1]=tile n0, b[2..3]=tile n0+8
static __device__ __forceinline__ void ldB(unsigned* b, const float* base, int n0, int c0, int ld) {
    const int lane = threadIdx.x & 31;
    int row = n0 + (lane & 7) + (lane >> 4) * 8;
    int col = c0 + ((lane >> 3) & 1) * 4;
    ldsm4(b, s2u(base + row * ld + col));
}

// ---------------------------------------------------------------------------
// Kernel 1: kqv = x @ w  (tf32 mma).  CTA 128x128, BK=32, 8 warps (2m x 4n)
// ---------------------------------------------------------------------------
__global__ __launch_bounds__(256) void gemm_kqv(const float* __restrict__ A,
                                                const float* __restrict__ W) {
    __shared__ __align__(16) float As[128 * LG];   // x tile  [m][k]
    __shared__ __align__(16) float WT[128 * LG];   // w^T tile [n][k]
    const int tid = threadIdx.x, lane = tid & 31, wid = tid >> 5;
    const int bm = blockIdx.y * 128, bn = blockIdx.x * 128;
    const int wm = (wid >> 2) * 64, wn = (wid & 3) * 32;

    float c[4][4][4];
#pragma unroll
    for (int i = 0; i < 4; i++)
#pragma unroll
        for (int j = 0; j < 4; j++)
#pragma unroll
            for (int e = 0; e < 4; e++) c[i][j][e] = 0.f;

    for (int k0 = 0; k0 < DM; k0 += 32) {
#pragma unroll
        for (int it = 0; it < 4; it++) {           // A tile: 128x32
            int idx = tid + it * 256;
            int r = idx >> 3, cc = (idx & 7) * 4;
            float4 v = *(const float4*)(A + (size_t)(bm + r) * DM + k0 + cc);
            v.x = tf32r(v.x); v.y = tf32r(v.y); v.z = tf32r(v.z); v.w = tf32r(v.w);
            *(float4*)&As[r * LG + cc] = v;
        }
#pragma unroll
        for (int it = 0; it < 4; it++) {           // W^T tile: [n][k]
            int idx = tid + it * 256;
            int n = idx & 127, kg = (idx >> 7) * 4;
            float4 v;
            v.x = tf32r(W[(size_t)(k0 + kg + 0) * D3 + bn + n]);
            v.y = tf32r(W[(size_t)(k0 + kg + 1) * D3 + bn + n]);
            v.z = tf32r(W[(size_t)(k0 + kg + 2) * D3 + bn + n]);
            v.w = tf32r(W[(size_t)(k0 + kg + 3) * D3 + bn + n]);
            *(float4*)&WT[n * LG + kg] = v;
        }
        __syncthreads();
#pragma unroll
        for (int ks = 0; ks < 4; ks++) {
            unsigned af[4][4], bf[2][4];
#pragma unroll
            for (int mt = 0; mt < 4; mt++) ldA(af[mt], As, wm + mt * 16, ks * 8, LG);
#pragma unroll
            for (int np = 0; np < 2; np++) ldB(bf[np], WT, wn + np * 16, ks * 8, LG);
#pragma unroll
            for (int mt = 0; mt < 4; mt++)
#pragma unroll
                for (int np = 0; np < 2; np++) {
                    mma_tf32(c[mt][np * 2],     af[mt], bf[np]);
                    mma_tf32(c[mt][np * 2 + 1], af[mt], bf[np] + 2);
                }
        }
        __syncthreads();
    }
#pragma unroll
    for (int mt = 0; mt < 4; mt++) {
        int r = bm + wm + mt * 16 + (lane >> 2);
#pragma unroll
        for (int nt = 0; nt < 4; nt++) {
            int col = bn + wn + nt * 8 + (lane & 3) * 2;
            *(float2*)&g_kqv[(size_t)r * D3 + col]       = make_float2(c[mt][nt][0], c[mt][nt][1]);
            *(float2*)&g_kqv[(size_t)(r + 8) * D3 + col] = make_float2(c[mt][nt][2], c[mt][nt][3]);
        }
    }
}

// ---------------------------------------------------------------------------
// Kernel 2: flash attention, tf32 mma, ALiBi + causal
// grid (32 q-tiles, 16 heads), 128 threads (4 warps), BM=128 (32 rows/warp), BN=64
// smem: QS[128][LA] | PS[128][LA] | KS[64][LA] | VT[64][LA]   (fp32, tf32-rounded)
// ---------------------------------------------------------------------------
__global__ __launch_bounds__(128) void attn_kernel(float* __restrict__ out) {
    extern __shared__ __align__(16) float sm[];
    float* QS = sm;                         // Q, pre-scaled by 1/32, persists
    float* PS = sm + 128 * LA;              // P (per-warp private 32 rows)
    float* KS = sm + 2 * 128 * LA;          // K tile [j][d]
    float* VT = sm + 2 * 128 * LA + 64 * LA; // V^T tile [d][j]

    const int tid = threadIdx.x, lane = tid & 31, wid = tid >> 5;
    const int h = blockIdx.y;
    const int qt = (int)gridDim.x - 1 - (int)blockIdx.x;   // heavy tiles first
    const int q0 = qt * 128;
    const int wr = wid * 32;
    const float slope = exp2f(-0.5f * (float)(h + 1));

    // load Q tile (offset DM), scale by 1/sqrt(D)=1/32, round to tf32
#pragma unroll
    for (int it = 0; it < 16; it++) {
        int idx = tid + it * 128;
        int r = idx >> 4, cc = (idx & 15) * 4;
        float4 v = *(const float4*)(g_kqv + (size_t)(q0 + r) * D3 + DM + h * 64 + cc);
        v.x = tf32r(v.x * 0.03125f); v.y = tf32r(v.y * 0.03125f);
        v.z = tf32r(v.z * 0.03125f); v.w = tf32r(v.w * 0.03125f);
        *(float4*)&QS[r * LA + cc] = v;
    }

    float o0[8][4], o1[8][4];
#pragma unroll
    for (int nt = 0; nt < 8; nt++)
#pragma unroll
        for (int e = 0; e < 4; e++) { o0[nt][e] = 0.f; o1[nt][e] = 0.f; }
    float m[4] = {-1e30f, -1e30f, -1e30f, -1e30f};
    float l[4] = {0.f, 0.f, 0.f, 0.f};

    const int ntiles = 2 * qt + 2;
    for (int t = 0; t < ntiles; t++) {
        const int kv0 = t * 64;
        // K tile [j][d]
#pragma unroll
        for (int it = 0; it < 8; it++) {
            int idx = tid + it * 128;
            int r = idx >> 4, cc = (idx & 15) * 4;
            float4 v = *(const float4*)(g_kqv + (size_t)(kv0 + r) * D3 + h * 64 + cc);
            v.x = tf32r(v.x); v.y = tf32r(v.y); v.z = tf32r(v.z); v.w = tf32r(v.w);
            *(float4*)&KS[r * LA + cc] = v;
        }
        // V^T tile [d][j]  (coalesced gmem reads per j, conflict-free STS.128)
#pragma unroll
        for (int it = 0; it < 8; it++) {
            int idx = tid + it * 128;
            int d = idx & 63, j0 = (idx >> 6) * 4;
            const float* gv = g_kqv + (size_t)(kv0 + j0) * D3 + 2 * DM + h * 64 + d;
            float4 v;
            v.x = tf32r(gv[0]); v.y = tf32r(gv[D3]); v.z = tf32r(gv[2 * D3]); v.w = tf32r(gv[3 * D3]);
            *(float4*)&VT[d * LA + j0] = v;
        }
        __syncthreads();   // also covers QS stores on t==0

        const bool skip = (kv0 > q0 + wr + 31);   // tile entirely above this warp's rows
        if (!skip) {
            // --- S = Q K^T ---
            float s0[8][4], s1[8][4];
#pragma unroll
            for (int nt = 0; nt < 8; nt++)
#pragma unroll
                for (int e = 0; e < 4; e++) { s0[nt][e] = 0.f; s1[nt][e] = 0.f; }
#pragma unroll
            for (int ks = 0; ks < 8; ks++) {
                unsigned qf0[4], qf1[4];
                ldA(qf0, QS, wr,      ks * 8, LA);
                ldA(qf1, QS, wr + 16, ks * 8, LA);
#pragma unroll
                for (int np = 0; np < 4; np++) {
                    unsigned bf[4];
                    ldB(bf, KS, np * 16, ks * 8, LA);
                    mma_tf32(s0[np * 2],     qf0, bf);
                    mma_tf32(s0[np * 2 + 1], qf0, bf + 2);
                    mma_tf32(s1[np * 2],     qf1, bf);
                    mma_tf32(s1[np * 2 + 1], qf1, bf + 2);
                }
            }

            // --- online softmax + P staging, per 16-row m-tile ---
            const bool maskT = (t >= ntiles - 2);
#pragma unroll
            for (int mt = 0; mt < 2; mt++) {
                float (*s)[4] = mt ? s1 : s0;
                float (*o)[4] = mt ? o1 : o0;
                const int gi0 = q0 + wr + mt * 16 + (lane >> 2);
                float ml0 = -1e30f, ml1 = -1e30f;
#pragma unroll
                for (int nt = 0; nt < 8; nt++) {
#pragma unroll
                    for (int e = 0; e < 2; e++) {
                        int gj = kv0 + nt * 8 + (lane & 3) * 2 + e;
                        float v0 = fmaf(slope, (float)(gj - gi0), s[nt][e]);
                        if (maskT && gj > gi0) v0 = -1e30f;
                        s[nt][e] = v0; ml0 = fmaxf(ml0, v0);
                        float v1 = fmaf(slope, (float)(gj - (gi0 + 8)), s[nt][2 + e]);
                        if (maskT && gj > gi0 + 8) v1 = -1e30f;
                        s[nt][2 + e] = v1; ml1 = fmaxf(ml1, v1);
                    }
                }
                ml0 = fmaxf(ml0, __shfl_xor_sync(0xffffffffu, ml0, 1));
                ml0 = fmaxf(ml0, __shfl_xor_sync(0xffffffffu, ml0, 2));
                ml1 = fmaxf(ml1, __shfl_xor_sync(0xffffffffu, ml1, 1));
                ml1 = fmaxf(ml1, __shfl_xor_sync(0xffffffffu, ml1, 2));
                float mn0 = fmaxf(m[2 * mt], ml0), mn1 = fmaxf(m[2 * mt + 1], ml1);
                float a0 = __expf(m[2 * mt] - mn0), a1 = __expf(m[2 * mt + 1] - mn1);
                m[2 * mt] = mn0; m[2 * mt + 1] = mn1;
                float rs0 = 0.f, rs1 = 0.f;
#pragma unroll
                for (int nt = 0; nt < 8; nt++) {
#pragma unroll
                    for (int e = 0; e < 2; e++) {
                        float p0 = __expf(s[nt][e] - mn0);     s[nt][e] = p0;     rs0 += p0;
                        float p1 = __expf(s[nt][2 + e] - mn1); s[nt][2 + e] = p1; rs1 += p1;
                    }
                }
                rs0 += __shfl_xor_sync(0xffffffffu, rs0, 1);
                rs0 += __shfl_xor_sync(0xffffffffu, rs0, 2);
                rs1 += __shfl_xor_sync(0xffffffffu, rs1, 1);
                rs1 += __shfl_xor_sync(0xffffffffu, rs1, 2);
                l[2 * mt]     = l[2 * mt] * a0 + rs0;
                l[2 * mt + 1] = l[2 * mt + 1] * a1 + rs1;
#pragma unroll
                for (int nt = 0; nt < 8; nt++) {
                    o[nt][0] *= a0; o[nt][1] *= a0; o[nt][2] *= a1; o[nt][3] *= a1;
                }
                // stage P (tf32-rounded) — own warp rows only
                const int pr = wr + mt * 16 + (lane >> 2);
                const int pc = (lane & 3) * 2;
#pragma unroll
                for (int nt = 0; nt < 8; nt++) {
                    *(float2*)&PS[pr * LA + nt * 8 + pc] =
                        make_float2(tf32r(s[nt][0]), tf32r(s[nt][1]));
                    *(float2*)&PS[(pr + 8) * LA + nt * 8 + pc] =
                        make_float2(tf32r(s[nt][2]), tf32r(s[nt][3]));
                }
            }
            __syncwarp();

            // --- O += P @ V ---
#pragma unroll
            for (int jk = 0; jk < 8; jk++) {
                unsigned pf0[4], pf1[4];
                ldA(pf0, PS, wr,      jk * 8, LA);
                ldA(pf1, PS, wr + 16, jk * 8, LA);
#pragma unroll
                for (int dp = 0; dp < 4; dp++) {
                    unsigned vf[4];
                    ldB(vf, VT, dp * 16, jk * 8, LA);
                    mma_tf32(o0[dp * 2],     pf0, vf);
                    mma_tf32(o0[dp * 2 + 1], pf0, vf + 2);
                    mma_tf32(o1[dp * 2],     pf1, vf);
                    mma_tf32(o1[dp * 2 + 1], pf1, vf + 2);
                }
            }
        }
        __syncthreads();   // all warps done before next tile overwrites KS/VT
    }

    // epilogue: normalize, write out[s][h*64+d]
    float rl[4] = {1.f / l[0], 1.f / l[1], 1.f / l[2], 1.f / l[3]};
#pragma unroll
    for (int mt = 0; mt < 2; mt++) {
        float (*o)[4] = mt ? o1 : o0;
        const int r = q0 + wr + mt * 16 + (lane >> 2);
#pragma unroll
        for (int nt = 0; nt < 8; nt++) {
            int col = h * 64 + nt * 8 + (lane & 3) * 2;
            *(float2*)&out[(size_t)r * DM + col] =
                make_float2(o[nt][0] * rl[2 * mt], o[nt][1] * rl[2 * mt]);
            *(float2*)&out[(size_t)(r + 8) * DM + col] =
                make_float2(o[nt][2] * rl[2 * mt + 1], o[nt][3] * rl[2 * mt + 1]);
        }
    }
}

// ---------------------------------------------------------------------------
// Launch
// ---------------------------------------------------------------------------
extern "C" void kernel_launch(void* const* d_in, const int* in_sizes, int n_in,
                              void* d_out, int out_size) {
    const float* x = (const float*)d_in[0];   // [1, 4096, 1024]
    const float* w = (const float*)d_in[1];   // [1024, 3072]
    float* out = (float*)d_out;

    const int attn_smem = (2 * 128 + 2 * 64) * LA * (int)sizeof(float);   // 104448 B
    cudaFuncSetAttribute(attn_kernel, cudaFuncAttributeMaxDynamicSharedMemorySize, attn_smem);

    gemm_kqv<<<dim3(D3 / 128, SEQ / 128), 256>>>(x, w);
    attn_kernel<<<dim3(SEQ / 128, NH), 128, attn_smem>>>(out);
}

// round 7
// speedup vs baseline: 4.9034x; 1.0110x over previous
#include <cuda_runtime.h>

#define SEQ 4096
#define DM  1024
#define NH  16
#define D3  3072
#define LA  68     // attn smem row stride (floats), 68 mod 32 == 4 -> ldmatrix conflict-free
#define LG  36     // gemm smem row stride (floats)

// fp32 scratch: kqv = x @ w_kqv (chunk order K|Q|V), values tf32-rounded, Q pre-scaled by 1/32
__device__ float g_kqv[SEQ * D3];
// V transposed per feature: g_vT[h*64+d][j]
__device__ float g_vT[DM * SEQ];

// ---------------------------------------------------------------------------
// helpers
// ---------------------------------------------------------------------------
static __device__ __forceinline__ unsigned s2u(const void* p) {
    return (unsigned)__cvta_generic_to_shared(p);
}
static __device__ __forceinline__ void ldsm4(unsigned* r, unsigned a) {
    asm volatile("ldmatrix.sync.aligned.m8n8.x4.shared.b16 {%0,%1,%2,%3}, [%4];"
                 : "=r"(r[0]), "=r"(r[1]), "=r"(r[2]), "=r"(r[3]) : "r"(a));
}
static __device__ __forceinline__ float tf32r(float x) {
    unsigned u; asm("cvt.rna.tf32.f32 %0, %1;" : "=r"(u) : "f"(x));
    return __uint_as_float(u);
}
static __device__ __forceinline__ void mma_tf32(float* c, const unsigned* a, const unsigned* b) {
    asm volatile("mma.sync.aligned.m16n8k8.row.col.f32.tf32.tf32.f32 "
                 "{%0,%1,%2,%3}, {%4,%5,%6,%7}, {%8,%9}, {%0,%1,%2,%3};"
                 : "+f"(c[0]), "+f"(c[1]), "+f"(c[2]), "+f"(c[3])
                 : "r"(a[0]), "r"(a[1]), "r"(a[2]), "r"(a[3]), "r"(b[0]), "r"(b[1]));
}
static __device__ __forceinline__ void ldA(unsigned* a, const float* base, int r0, int c0, int ld) {
    const int lane = threadIdx.x & 31;
    int row = r0 + (lane & 7) + ((lane >> 3) & 1) * 8;
    int col = c0 + (lane >> 4) * 4;
    ldsm4(a, s2u(base + row * ld + col));
}
static __device__ __forceinline__ void ldB(unsigned* b, const float* base, int n0, int c0, int ld) {
    const int lane = threadIdx.x & 31;
    int row = n0 + (lane & 7) + (lane >> 4) * 8;
    int col = c0 + ((lane >> 3) & 1) * 4;
    ldsm4(b, s2u(base + row * ld + col));
}
static __device__ __forceinline__ void cpa16(unsigned s, const void* g) {
    asm volatile("cp.async.cg.shared.global [%0], [%1], 16;" :: "r"(s), "l"(g) : "memory");
}
#define CP_COMMIT() asm volatile("cp.async.commit_group;" ::: "memory")
#define CP_WAIT(n)  asm volatile("cp.async.wait_group %0;" :: "n"(n) : "memory")

// ---------------------------------------------------------------------------
// Kernel 1: kqv = x @ w (tf32 mma). CTA 128x128, BK=32, 8 warps (2m x 4n)
// Epilogue: tf32-round; Q chunk (cols [1024,2048)) pre-scaled by 1/32.
// ---------------------------------------------------------------------------
__global__ __launch_bounds__(256) void gemm_kqv(const float* __restrict__ A,
                                                const float* __restrict__ W) {
    __shared__ __align__(16) float As[128 * LG];
    __shared__ __align__(16) float WT[128 * LG];
    const int tid = threadIdx.x, lane = tid & 31, wid = tid >> 5;
    const int bm = blockIdx.y * 128, bn = blockIdx.x * 128;
    const int wm = (wid >> 2) * 64, wn = (wid & 3) * 32;

    float c[4][4][4];
#pragma unroll
    for (int i = 0; i < 4; i++)
#pragma unroll
        for (int j = 0; j < 4; j++)
#pragma unroll
            for (int e = 0; e < 4; e++) c[i][j][e] = 0.f;

    for (int k0 = 0; k0 < DM; k0 += 32) {
#pragma unroll
        for (int it = 0; it < 4; it++) {
            int idx = tid + it * 256;
            int r = idx >> 3, cc = (idx & 7) * 4;
            float4 v = *(const float4*)(A + (size_t)(bm + r) * DM + k0 + cc);
            v.x = tf32r(v.x); v.y = tf32r(v.y); v.z = tf32r(v.z); v.w = tf32r(v.w);
            *(float4*)&As[r * LG + cc] = v;
        }
#pragma unroll
        for (int it = 0; it < 4; it++) {
            int idx = tid + it * 256;
            int n = idx & 127, kg = (idx >> 7) * 4;
            float4 v;
            v.x = tf32r(W[(size_t)(k0 + kg + 0) * D3 + bn + n]);
            v.y = tf32r(W[(size_t)(k0 + kg + 1) * D3 + bn + n]);
            v.z = tf32r(W[(size_t)(k0 + kg + 2) * D3 + bn + n]);
            v.w = tf32r(W[(size_t)(k0 + kg + 3) * D3 + bn + n]);
            *(float4*)&WT[n * LG + kg] = v;
        }
        __syncthreads();
#pragma unroll
        for (int ks = 0; ks < 4; ks++) {
            unsigned af[4][4], bf[2][4];
#pragma unroll
            for (int mt = 0; mt < 4; mt++) ldA(af[mt], As, wm + mt * 16, ks * 8, LG);
#pragma unroll
            for (int np = 0; np < 2; np++) ldB(bf[np], WT, wn + np * 16, ks * 8, LG);
#pragma unroll
            for (int mt = 0; mt < 4; mt++)
#pragma unroll
                for (int np = 0; np < 2; np++) {
                    mma_tf32(c[mt][np * 2],     af[mt], bf[np]);
                    mma_tf32(c[mt][np * 2 + 1], af[mt], bf[np] + 2);
                }
        }
        __syncthreads();
    }
    const float scl = (bn >= DM && bn < 2 * DM) ? 0.03125f : 1.0f;   // pre-scale Q by 1/sqrt(D)
#pragma unroll
    for (int mt = 0; mt < 4; mt++) {
        int r = bm + wm + mt * 16 + (lane >> 2);
#pragma unroll
        for (int nt = 0; nt < 4; nt++) {
            int col = bn + wn + nt * 8 + (lane & 3) * 2;
            *(float2*)&g_kqv[(size_t)r * D3 + col] =
                make_float2(tf32r(c[mt][nt][0] * scl), tf32r(c[mt][nt][1] * scl));
            *(float2*)&g_kqv[(size_t)(r + 8) * D3 + col] =
                make_float2(tf32r(c[mt][nt][2] * scl), tf32r(c[mt][nt][3] * scl));
        }
    }
}

// ---------------------------------------------------------------------------
// Kernel 1.5: transpose V chunk -> g_vT[c][j]   (c = h*64+d, j = seq)
// ---------------------------------------------------------------------------
__global__ __launch_bounds__(256) void vtrans_kernel() {
    __shared__ float t[32][33];
    const int x = threadIdx.x, y = threadIdx.y;       // 32 x 8
    const int j0 = blockIdx.x * 32, c0 = blockIdx.y * 32;
#pragma unroll
    for (int k = 0; k < 4; k++)
        t[y + k * 8][x] = g_kqv[(size_t)(j0 + y + k * 8) * D3 + 2 * DM + c0 + x];
    __syncthreads();
#pragma unroll
    for (int k = 0; k < 4; k++)
        g_vT[(size_t)(c0 + y + k * 8) * SEQ + j0 + x] = t[x][y + k * 8];
}

// ---------------------------------------------------------------------------
// Kernel 2: flash attention, tf32 mma, ALiBi + causal.
// grid (32 q-tiles, 16 heads), 128 threads (4 warps, 32 rows each), BN=64.
// cp.async single-buffer pipeline: V(t) overlaps S(t); K(t+1) overlaps softmax+PV(t).
// smem: QS[128][LA] | PS[128][LA] | KS[64][LA] | VT[64][LA]  = 104448 B (2 CTAs/SM)
// ---------------------------------------------------------------------------
__global__ __launch_bounds__(128, 2) void attn_kernel(float* __restrict__ out) {
    extern __shared__ __align__(16) float sm[];
    float* QS = sm;                  // Q (pre-scaled, tf32), persists
    float* PS = sm + 128 * LA;       // P staging (per-warp private rows)
    float* KS = sm + 256 * LA;       // K tile [j][d]
    float* VT = sm + 320 * LA;       // V^T tile [d][j]

    const int tid = threadIdx.x, lane = tid & 31, wid = tid >> 5;
    const int h = blockIdx.y;
    const int qt = (int)gridDim.x - 1 - (int)blockIdx.x;   // heavy tiles first
    const int q0 = qt * 128;
    const int wr = wid * 32;
    const float slope = exp2f(-0.5f * (float)(h + 1));
    const int nt = 2 * qt + 2;

    // prologue: async-load Q tile + K(0)  (one group)
#pragma unroll
    for (int p = 0; p < 16; p++) {
        int ch = tid + p * 128;
        int r = ch >> 4, c4 = (ch & 15) * 4;
        cpa16(s2u(&QS[r * LA + c4]), g_kqv + (size_t)(q0 + r) * D3 + DM + h * 64 + c4);
    }
#pragma unroll
    for (int p = 0; p < 8; p++) {
        int ch = tid + p * 128;
        int r = ch >> 4, c4 = (ch & 15) * 4;
        cpa16(s2u(&KS[r * LA + c4]), g_kqv + (size_t)r * D3 + h * 64 + c4);
    }
    CP_COMMIT();

    float o0[8][4], o1[8][4];
#pragma unroll
    for (int ntl = 0; ntl < 8; ntl++)
#pragma unroll
        for (int e = 0; e < 4; e++) { o0[ntl][e] = 0.f; o1[ntl][e] = 0.f; }
    float m[4] = {-1e30f, -1e30f, -1e30f, -1e30f};
    float l[4] = {0.f, 0.f, 0.f, 0.f};

    for (int t = 0; t < nt; t++) {
        const int kv0 = t * 64;
        const bool active = (kv0 <= q0 + wr + 31);

        // issue V(t): VT[64][64] = 1024 16B-chunks; VT[d][j] from g_vT row h*64+d
#pragma unroll
        for (int p = 0; p < 8; p++) {
            int ch = tid + p * 128;
            int d = ch >> 4, j4 = (ch & 15) * 4;
            cpa16(s2u(&VT[d * LA + j4]), g_vT + (size_t)(h * 64 + d) * SEQ + kv0 + j4);
        }
        CP_COMMIT();

        CP_WAIT(1);          // K(t) (+Q on t==0) ready; V(t) may still fly
        __syncthreads();

        float s0[8][4], s1[8][4];
        if (active) {
#pragma unroll
            for (int ntl = 0; ntl < 8; ntl++)
#pragma unroll
                for (int e = 0; e < 4; e++) { s0[ntl][e] = 0.f; s1[ntl][e] = 0.f; }
#pragma unroll
            for (int ks = 0; ks < 8; ks++) {
                unsigned qf0[4], qf1[4];
                ldA(qf0, QS, wr,      ks * 8, LA);
                ldA(qf1, QS, wr + 16, ks * 8, LA);
#pragma unroll
                for (int np = 0; np < 4; np++) {
                    unsigned bf[4];
                    ldB(bf, KS, np * 16, ks * 8, LA);
                    mma_tf32(s0[np * 2],     qf0, bf);
                    mma_tf32(s0[np * 2 + 1], qf0, bf + 2);
                    mma_tf32(s1[np * 2],     qf1, bf);
                    mma_tf32(s1[np * 2 + 1], qf1, bf + 2);
                }
            }
        }
        __syncthreads();     // all warps done reading KS

        // prefetch K(t+1) (clamped; overlaps softmax + PV)
        {
            const int kvn = (t + 1 < nt ? t + 1 : t) * 64;
#pragma unroll
            for (int p = 0; p < 8; p++) {
                int ch = tid + p * 128;
                int r = ch >> 4, c4 = (ch & 15) * 4;
                cpa16(s2u(&KS[r * LA + c4]), g_kqv + (size_t)(kvn + r) * D3 + h * 64 + c4);
            }
            CP_COMMIT();
        }

        if (active) {
            const bool maskT = (t >= nt - 2);
#pragma unroll
            for (int mt = 0; mt < 2; mt++) {
                float (*s)[4] = mt ? s1 : s0;
                float (*o)[4] = mt ? o1 : o0;
                const int gi0 = q0 + wr + mt * 16 + (lane >> 2);
                float ml0 = -1e30f, ml1 = -1e30f;
#pragma unroll
                for (int ntl = 0; ntl < 8; ntl++) {
#pragma unroll
                    for (int e = 0; e < 2; e++) {
                        int gj = kv0 + ntl * 8 + (lane & 3) * 2 + e;
                        float v0 = fmaf(slope, (float)(gj - gi0), s[ntl][e]);
                        if (maskT && gj > gi0) v0 = -1e30f;
                        s[ntl][e] = v0; ml0 = fmaxf(ml0, v0);
                        float v1 = fmaf(slope, (float)(gj - (gi0 + 8)), s[ntl][2 + e]);
                        if (maskT && gj > gi0 + 8) v1 = -1e30f;
                        s[ntl][2 + e] = v1; ml1 = fmaxf(ml1, v1);
                    }
                }
                ml0 = fmaxf(ml0, __shfl_xor_sync(0xffffffffu, ml0, 1));
                ml0 = fmaxf(ml0, __shfl_xor_sync(0xffffffffu, ml0, 2));
                ml1 = fmaxf(ml1, __shfl_xor_sync(0xffffffffu, ml1, 1));
                ml1 = fmaxf(ml1, __shfl_xor_sync(0xffffffffu, ml1, 2));
                float mn0 = fmaxf(m[2 * mt], ml0), mn1 = fmaxf(m[2 * mt + 1], ml1);
                float a0 = __expf(m[2 * mt] - mn0), a1 = __expf(m[2 * mt + 1] - mn1);
                m[2 * mt] = mn0; m[2 * mt + 1] = mn1;
                float rs0 = 0.f, rs1 = 0.f;
#pragma unroll
                for (int ntl = 0; ntl < 8; ntl++) {
#pragma unroll
                    for (int e = 0; e < 2; e++) {
                        float p0 = __expf(s[ntl][e] - mn0);     s[ntl][e] = p0;     rs0 += p0;
                        float p1 = __expf(s[ntl][2 + e] - mn1); s[ntl][2 + e] = p1; rs1 += p1;
                    }
                }
                rs0 += __shfl_xor_sync(0xffffffffu, rs0, 1);
                rs0 += __shfl_xor_sync(0xffffffffu, rs0, 2);
                rs1 += __shfl_xor_sync(0xffffffffu, rs1, 1);
                rs1 += __shfl_xor_sync(0xffffffffu, rs1, 2);
                l[2 * mt]     = l[2 * mt] * a0 + rs0;
                l[2 * mt + 1] = l[2 * mt + 1] * a1 + rs1;
#pragma unroll
                for (int ntl = 0; ntl < 8; ntl++) {
                    o[ntl][0] *= a0; o[ntl][1] *= a0; o[ntl][2] *= a1; o[ntl][3] *= a1;
                }
                const int pr = wr + mt * 16 + (lane >> 2);
                const int pc = (lane & 3) * 2;
#pragma unroll
                for (int ntl = 0; ntl < 8; ntl++) {
                    *(float2*)&PS[pr * LA + ntl * 8 + pc] =
                        make_float2(tf32r(s[ntl][0]), tf32r(s[ntl][1]));
                    *(float2*)&PS[(pr + 8) * LA + ntl * 8 + pc] =
                        make_float2(tf32r(s[ntl][2]), tf32r(s[ntl][3]));
                }
            }
            __syncwarp();
        }

        CP_WAIT(1);          // V(t) ready; K(t+1) may still fly
        __syncthreads();

        if (active) {
#pragma unroll
            for (int jk = 0; jk < 8; jk++) {
                unsigned pf0[4], pf1[4];
                ldA(pf0, PS, wr,      jk * 8, LA);
                ldA(pf1, PS, wr + 16, jk * 8, LA);
#pragma unroll
                for (int dp = 0; dp < 4; dp++) {
                    unsigned vf[4];
                    ldB(vf, VT, dp * 16, jk * 8, LA);
                    mma_tf32(o0[dp * 2],     pf0, vf);
                    mma_tf32(o0[dp * 2 + 1], pf0, vf + 2);
                    mma_tf32(o1[dp * 2],     pf1, vf);
                    mma_tf32(o1[dp * 2 + 1], pf1, vf + 2);
                }
            }
        }
        __syncthreads();     // all done with VT before next iteration's V issue
    }

    float rl[4] = {1.f / l[0], 1.f / l[1], 1.f / l[2], 1.f / l[3]};
#pragma unroll
    for (int mt = 0; mt < 2; mt++) {
        float (*o)[4] = mt ? o1 : o0;
        const int r = q0 + wr + mt * 16 + (lane >> 2);
#pragma unroll
        for (int ntl = 0; ntl < 8; ntl++) {
            int col = h * 64 + ntl * 8 + (lane & 3) * 2;
            *(float2*)&out[(size_t)r * DM + col] =
                make_float2(o[ntl][0] * rl[2 * mt], o[ntl][1] * rl[2 * mt]);
            *(float2*)&out[(size_t)(r + 8) * DM + col] =
                make_float2(o[ntl][2] * rl[2 * mt + 1], o[ntl][3] * rl[2 * mt + 1]);
        }
    }
}

// ---------------------------------------------------------------------------
// Launch
// ---------------------------------------------------------------------------
extern "C" void kernel_launch(void* const* d_in, const int* in_sizes, int n_in,
                              void* d_out, int out_size) {
    const float* x = (const float*)d_in[0];   // [1, 4096, 1024]
    const float* w = (const float*)d_in[1];   // [1024, 3072]
    float* out = (float*)d_out;

    const int attn_smem = 384 * LA * (int)sizeof(float);   // 104448 B
    cudaFuncSetAttribute(attn_kernel, cudaFuncAttributeMaxDynamicSharedMemorySize, attn_smem);

    gemm_kqv<<<dim3(D3 / 128, SEQ / 128), 256>>>(x, w);
    vtrans_kernel<<<dim3(SEQ / 32, DM / 32), dim3(32, 8)>>>();
    attn_kernel<<<dim3(SEQ / 128, NH), 128, attn_smem>>>(out);
}